// round 2
// baseline (speedup 1.0000x reference)
#include <cuda_runtime.h>
#include <math.h>

#define N_NODES 50000
#define N_EDGES 600000
#define IN_CH   128
#define HID1    256
#define HID2    128

// ---------------- device scratch (static allocation, allowed) ----------------
__device__ int   g_counts[N_NODES];
__device__ int   g_rowptr[N_NODES + 1];
__device__ int   g_cursor[N_NODES];
__device__ float g_dinv[N_NODES];
__device__ int   g_col[N_EDGES];
__device__ float g_bufA[(size_t)N_NODES * 256];   // hs1, later hs2
__device__ float g_bufB[(size_t)N_NODES * 256];   // h1,  later h2
__device__ float g_hs3[(size_t)N_NODES * 2];

// ---------------- graph construction ----------------
__global__ void k_zero_counts() {
    int i = blockIdx.x * blockDim.x + threadIdx.x;
    if (i < N_NODES) g_counts[i] = 0;
}

__global__ void k_count(const int* __restrict__ dst) {
    int e = blockIdx.x * blockDim.x + threadIdx.x;
    if (e < N_EDGES) atomicAdd(&g_counts[dst[e]], 1);
}

// single-block scan over 50000 counts -> exclusive rowptr
__global__ void k_scan() {
    __shared__ int sh[1024];
    __shared__ int carry;
    int tid = threadIdx.x;
    if (tid == 0) carry = 0;
    __syncthreads();
    for (int base = 0; base < N_NODES; base += 1024) {
        int i = base + tid;
        int v = (i < N_NODES) ? g_counts[i] : 0;
        sh[tid] = v;
        __syncthreads();
        #pragma unroll
        for (int off = 1; off < 1024; off <<= 1) {
            int t = (tid >= off) ? sh[tid - off] : 0;
            __syncthreads();
            sh[tid] += t;
            __syncthreads();
        }
        int inc = sh[tid] + carry;
        if (i < N_NODES) g_rowptr[i + 1] = inc;
        __syncthreads();
        if (tid == 1023) carry = inc;
        __syncthreads();
    }
    if (tid == 0) g_rowptr[0] = 0;
}

__global__ void k_dinv_cursor() {
    int i = blockIdx.x * blockDim.x + threadIdx.x;
    if (i < N_NODES) {
        g_dinv[i]   = rsqrtf((float)(g_counts[i] + 1));  // +1 self loop
        g_cursor[i] = g_rowptr[i];
    }
}

__global__ void k_fill(const int* __restrict__ src,
                       const int* __restrict__ dst) {
    int e = blockIdx.x * blockDim.x + threadIdx.x;
    if (e < N_EDGES) {
        int d = dst[e];
        int pos = atomicAdd(&g_cursor[d], 1);
        g_col[pos] = src[e];
    }
}

// ---------------- fp32 tiled GEMM: out[r,c] = dinv[r] * sum_k A[r,k]*W[k,c] ----------------
// BM=64, BN=64, BK=16, 256 threads, 4x4 microtile
__global__ __launch_bounds__(256) void k_gemm(const float* __restrict__ A,
                                              const float* __restrict__ W,
                                              float* __restrict__ out,
                                              int N, int K, int M) {
    __shared__ float As[16][64];
    __shared__ float Bs[16][64];
    int tid = threadIdx.x;
    int tx = tid & 15, ty = tid >> 4;
    int rowBase = blockIdx.x * 64;
    int colBase = blockIdx.y * 64;

    int aRow = tid >> 2;          // 0..63
    int aK   = (tid & 3) * 4;     // 0,4,8,12
    int bK   = tid >> 4;          // 0..15
    int bC   = (tid & 15) * 4;    // 0..60

    float acc[4][4];
    #pragma unroll
    for (int i = 0; i < 4; i++)
        #pragma unroll
        for (int j = 0; j < 4; j++) acc[i][j] = 0.f;

    for (int k0 = 0; k0 < K; k0 += 16) {
        float4 av = make_float4(0.f, 0.f, 0.f, 0.f);
        int gr = rowBase + aRow;
        if (gr < N) av = *(const float4*)&A[(size_t)gr * K + k0 + aK];
        As[aK + 0][aRow] = av.x;
        As[aK + 1][aRow] = av.y;
        As[aK + 2][aRow] = av.z;
        As[aK + 3][aRow] = av.w;

        float4 bv = *(const float4*)&W[(size_t)(k0 + bK) * M + colBase + bC];
        *(float4*)&Bs[bK][bC] = bv;
        __syncthreads();

        #pragma unroll
        for (int k = 0; k < 16; k++) {
            float4 a = *(float4*)&As[k][ty * 4];
            float4 b = *(float4*)&Bs[k][tx * 4];
            float ar[4] = {a.x, a.y, a.z, a.w};
            float br[4] = {b.x, b.y, b.z, b.w};
            #pragma unroll
            for (int i = 0; i < 4; i++)
                #pragma unroll
                for (int j = 0; j < 4; j++)
                    acc[i][j] += ar[i] * br[j];
        }
        __syncthreads();
    }

    #pragma unroll
    for (int i = 0; i < 4; i++) {
        int gr = rowBase + ty * 4 + i;
        if (gr < N) {
            float s = g_dinv[gr];
            float4 o = make_float4(acc[i][0] * s, acc[i][1] * s,
                                   acc[i][2] * s, acc[i][3] * s);
            *(float4*)&out[(size_t)gr * M + colBase + tx * 4] = o;
        }
    }
}

// ---------------- small GEMM (K=128, M=2): warp per row ----------------
__global__ __launch_bounds__(256) void k_gemm3(const float* __restrict__ A,
                                               const float* __restrict__ W3,
                                               float* __restrict__ out) {
    __shared__ float w[256];  // 128 x 2
    int tid = threadIdx.x;
    w[tid] = W3[tid];
    __syncthreads();
    int warp = (blockIdx.x * blockDim.x + tid) >> 5;
    int lane = tid & 31;
    if (warp >= N_NODES) return;
    float4 h = *(const float4*)&A[(size_t)warp * 128 + lane * 4];
    float hv[4] = {h.x, h.y, h.z, h.w};
    float a0 = 0.f, a1 = 0.f;
    #pragma unroll
    for (int j = 0; j < 4; j++) {
        int k = lane * 4 + j;
        a0 += hv[j] * w[k * 2 + 0];
        a1 += hv[j] * w[k * 2 + 1];
    }
    #pragma unroll
    for (int off = 16; off; off >>= 1) {
        a0 += __shfl_down_sync(0xFFFFFFFFu, a0, off);
        a1 += __shfl_down_sync(0xFFFFFFFFu, a1, off);
    }
    if (lane == 0) {
        float s = g_dinv[warp];
        out[(size_t)warp * 2 + 0] = a0 * s;
        out[(size_t)warp * 2 + 1] = a1 * s;
    }
}

// ---------------- aggregation: warp per node, gather from CSR ----------------
// out[i] = relu(dinv[i]*(sum_{e in(i)} hs[src] + hs[i]) + b)
template <int CH>
__global__ __launch_bounds__(256) void k_agg(const float* __restrict__ hs,
                                             const float* __restrict__ bias,
                                             float* __restrict__ out) {
    constexpr int V = CH / 128;  // float4 chunks per lane
    int warp = (blockIdx.x * blockDim.x + threadIdx.x) >> 5;
    int lane = threadIdx.x & 31;
    if (warp >= N_NODES) return;

    float4 acc[V];
    #pragma unroll
    for (int v = 0; v < V; v++)
        acc[v] = *(const float4*)&hs[(size_t)warp * CH + v * 128 + lane * 4];

    int e = g_rowptr[warp], eEnd = g_rowptr[warp + 1];
    for (; e + 1 < eEnd; e += 2) {
        int s0 = g_col[e], s1 = g_col[e + 1];
        #pragma unroll
        for (int v = 0; v < V; v++) {
            float4 x0 = *(const float4*)&hs[(size_t)s0 * CH + v * 128 + lane * 4];
            float4 x1 = *(const float4*)&hs[(size_t)s1 * CH + v * 128 + lane * 4];
            acc[v].x += x0.x + x1.x;
            acc[v].y += x0.y + x1.y;
            acc[v].z += x0.z + x1.z;
            acc[v].w += x0.w + x1.w;
        }
    }
    if (e < eEnd) {
        int s0 = g_col[e];
        #pragma unroll
        for (int v = 0; v < V; v++) {
            float4 x0 = *(const float4*)&hs[(size_t)s0 * CH + v * 128 + lane * 4];
            acc[v].x += x0.x;
            acc[v].y += x0.y;
            acc[v].z += x0.z;
            acc[v].w += x0.w;
        }
    }

    float d = g_dinv[warp];
    #pragma unroll
    for (int v = 0; v < V; v++) {
        int c = v * 128 + lane * 4;
        float4 b = *(const float4*)&bias[c];
        float4 o;
        o.x = fmaxf(acc[v].x * d + b.x, 0.f);
        o.y = fmaxf(acc[v].y * d + b.y, 0.f);
        o.z = fmaxf(acc[v].z * d + b.z, 0.f);
        o.w = fmaxf(acc[v].w * d + b.w, 0.f);
        *(float4*)&out[(size_t)warp * CH + c] = o;
    }
}

// ---------------- final aggregation + log_softmax (CH=2) ----------------
__global__ __launch_bounds__(256) void k_agg3(const float* __restrict__ b3,
                                              float* __restrict__ out) {
    int i = blockIdx.x * blockDim.x + threadIdx.x;
    if (i >= N_NODES) return;
    float2 acc = *(const float2*)&g_hs3[(size_t)i * 2];
    int e = g_rowptr[i], eE = g_rowptr[i + 1];
    for (; e < eE; e++) {
        int s = g_col[e];
        float2 x = *(const float2*)&g_hs3[(size_t)s * 2];
        acc.x += x.x;
        acc.y += x.y;
    }
    float d = g_dinv[i];
    float v0 = acc.x * d + b3[0];
    float v1 = acc.y * d + b3[1];
    float m = fmaxf(v0, v1);
    float lse = m + logf(expf(v0 - m) + expf(v1 - m));
    out[(size_t)i * 2 + 0] = v0 - lse;
    out[(size_t)i * 2 + 1] = v1 - lse;
}

// ---------------- launch ----------------
extern "C" void kernel_launch(void* const* d_in, const int* in_sizes, int n_in,
                              void* d_out, int out_size) {
    const float* x  = (const float*)d_in[0];
    const float* W1 = (const float*)d_in[1];
    const float* b1 = (const float*)d_in[2];
    const float* W2 = (const float*)d_in[3];
    const float* b2 = (const float*)d_in[4];
    const float* W3 = (const float*)d_in[5];
    const float* b3 = (const float*)d_in[6];
    const int* ei   = (const int*)d_in[7];   // int32 (JAX demotes int64 with x64 disabled)
    const int* src  = ei;
    const int* dst  = ei + N_EDGES;
    float* out = (float*)d_out;

    float *bufA, *bufB, *hs3;
    cudaGetSymbolAddress((void**)&bufA, g_bufA);
    cudaGetSymbolAddress((void**)&bufB, g_bufB);
    cudaGetSymbolAddress((void**)&hs3, g_hs3);

    const int TB = 256;
    // graph build
    k_zero_counts<<<(N_NODES + TB - 1) / TB, TB>>>();
    k_count<<<(N_EDGES + TB - 1) / TB, TB>>>(dst);
    k_scan<<<1, 1024>>>();
    k_dinv_cursor<<<(N_NODES + TB - 1) / TB, TB>>>();
    k_fill<<<(N_EDGES + TB - 1) / TB, TB>>>(src, dst);

    int gemmRows = (N_NODES + 63) / 64;
    int aggBlocks = (N_NODES * 32 + TB - 1) / TB;

    // layer 1: hs1 = dinv * (x @ W1)  [N, 256]
    k_gemm<<<dim3(gemmRows, HID1 / 64), TB>>>(x, W1, bufA, N_NODES, IN_CH, HID1);
    k_agg<HID1><<<aggBlocks, TB>>>(bufA, b1, bufB);

    // layer 2: hs2 = dinv * (h1 @ W2)  [N, 128]
    k_gemm<<<dim3(gemmRows, HID2 / 64), TB>>>(bufB, W2, bufA, N_NODES, HID1, HID2);
    k_agg<HID2><<<aggBlocks, TB>>>(bufA, b2, bufB);

    // layer 3: hs3 = dinv * (h2 @ W3)  [N, 2]
    k_gemm3<<<aggBlocks, TB>>>(bufB, W3, hs3);
    k_agg3<<<(N_NODES + TB - 1) / TB, TB>>>(b3, out);
}

// round 3
// speedup vs baseline: 1.3490x; 1.3490x over previous
#include <cuda_runtime.h>
#include <math.h>
#include <stdint.h>

#define N_NODES 50000
#define N_EDGES 600000
#define IN_CH   128
#define HID1    256
#define HID2    128
#define SCAN_BLKS 196   // ceil(50000/256)

// ---------------- device scratch ----------------
__device__ int   g_counts[N_NODES];
__device__ int   g_rowptr[N_NODES + 1];
__device__ int   g_cursor[N_NODES];
__device__ float g_dinv[N_NODES];
__device__ int   g_col[N_EDGES];
__device__ int   g_bsum[SCAN_BLKS];
__device__ int   g_boff[SCAN_BLKS];
__device__ float g_bufA[(size_t)N_NODES * 256];
__device__ float g_bufB[(size_t)N_NODES * 256];
__device__ float g_hs3[(size_t)N_NODES * 2];

// ---------------- graph construction ----------------
__global__ void k_zero_counts() {
    int i = blockIdx.x * blockDim.x + threadIdx.x;
    if (i < N_NODES) g_counts[i] = 0;
}

__global__ void k_count(const int* __restrict__ dst) {
    int e = blockIdx.x * blockDim.x + threadIdx.x;
    if (e < N_EDGES) atomicAdd(&g_counts[dst[e]], 1);
}

// phase 1: per-block inclusive scan of counts, write partials + block sums
__global__ __launch_bounds__(256) void k_scan1() {
    __shared__ int sh[256];
    int b = blockIdx.x, t = threadIdx.x;
    int i = b * 256 + t;
    int v = (i < N_NODES) ? g_counts[i] : 0;
    sh[t] = v;
    __syncthreads();
    #pragma unroll
    for (int off = 1; off < 256; off <<= 1) {
        int u = (t >= off) ? sh[t - off] : 0;
        __syncthreads();
        sh[t] += u;
        __syncthreads();
    }
    if (i < N_NODES) g_rowptr[i + 1] = sh[t];
    if (t == 255) g_bsum[b] = sh[255];
}

// phase 2: exclusive scan over block sums (single block)
__global__ __launch_bounds__(256) void k_scan2() {
    __shared__ int sh[256];
    int t = threadIdx.x;
    int v = (t < SCAN_BLKS) ? g_bsum[t] : 0;
    sh[t] = v;
    __syncthreads();
    #pragma unroll
    for (int off = 1; off < 256; off <<= 1) {
        int u = (t >= off) ? sh[t - off] : 0;
        __syncthreads();
        sh[t] += u;
        __syncthreads();
    }
    if (t < SCAN_BLKS) g_boff[t] = sh[t] - v;  // exclusive
}

// phase 3: add block offsets; compute dinv + cursors
__global__ __launch_bounds__(256) void k_scan3() {
    int b = blockIdx.x, t = threadIdx.x;
    int i = b * 256 + t;
    if (i < N_NODES) {
        int rp1 = g_rowptr[i + 1] + g_boff[b];
        g_rowptr[i + 1] = rp1;
        int c = g_counts[i];
        g_cursor[i] = rp1 - c;
        g_dinv[i] = rsqrtf((float)(c + 1));
    }
    if (i == 0) g_rowptr[0] = 0;
}

__global__ void k_fill(const int* __restrict__ src,
                       const int* __restrict__ dst) {
    int e = blockIdx.x * blockDim.x + threadIdx.x;
    if (e < N_EDGES) {
        int d = dst[e];
        int pos = atomicAdd(&g_cursor[d], 1);
        g_col[pos] = src[e];
    }
}

// xs = dinv (x)  row-scale, CH=128
__global__ __launch_bounds__(256) void k_scale(const float* __restrict__ x,
                                               float* __restrict__ xs) {
    int idx = blockIdx.x * blockDim.x + threadIdx.x;   // float4 index
    if (idx >= N_NODES * 32) return;
    int row = idx >> 5;
    float d = g_dinv[row];
    float4 v = *(const float4*)&x[(size_t)idx * 4];
    v.x *= d; v.y *= d; v.z *= d; v.w *= d;
    *(float4*)&xs[(size_t)idx * 4] = v;
}

// ---------------- TF32 split helpers + mma ----------------
__device__ __forceinline__ void tf32_split(float x, uint32_t& hi, uint32_t& lo) {
    asm("cvt.rna.tf32.f32 %0, %1;" : "=r"(hi) : "f"(x));
    float r = x - __uint_as_float(hi);
    asm("cvt.rna.tf32.f32 %0, %1;" : "=r"(lo) : "f"(r));
}

__device__ __forceinline__ void mma_tf32(float* c, uint32_t a0, uint32_t a1,
                                         uint32_t a2, uint32_t a3,
                                         uint32_t b0, uint32_t b1) {
    asm volatile(
        "mma.sync.aligned.m16n8k8.row.col.f32.tf32.tf32.f32 "
        "{%0,%1,%2,%3}, {%4,%5,%6,%7}, {%8,%9}, {%0,%1,%2,%3};"
        : "+f"(c[0]), "+f"(c[1]), "+f"(c[2]), "+f"(c[3])
        : "r"(a0), "r"(a1), "r"(a2), "r"(a3), "r"(b0), "r"(b1));
}

// ---------------- 3xTF32 GEMM: out[N,M] = A[N,K] @ W[K,M] (+epilogue) ----------------
// BM=128, BN=64, BK=16; 8 warps: 4 along M (32 rows each) x 2 along N (32 cols each)
// EPI 0: out = relu(acc + bias[col]);  EPI 1: out = dinv[row] * acc
#define AS_STRIDE 20
#define BS_STRIDE 72
template <int EPI>
__global__ __launch_bounds__(256) void k_gemm_tf32(const float* __restrict__ A,
                                                   const float* __restrict__ W,
                                                   const float* __restrict__ bias,
                                                   float* __restrict__ out,
                                                   int N, int K, int M) {
    __shared__ float As_hi[128 * AS_STRIDE];
    __shared__ float As_lo[128 * AS_STRIDE];
    __shared__ float Bs_hi[16 * BS_STRIDE];
    __shared__ float Bs_lo[16 * BS_STRIDE];

    const int tid = threadIdx.x;
    const int lane = tid & 31;
    const int warp = tid >> 5;
    const int gid = lane >> 2;     // 0..7
    const int tig = lane & 3;      // 0..3
    const int warpM = warp & 3;    // 0..3
    const int warpN = warp >> 2;   // 0..1
    const int rowBase = blockIdx.x * 128;
    const int colBase = blockIdx.y * 64;

    float acc[2][4][4];
    #pragma unroll
    for (int mt = 0; mt < 2; mt++)
        #pragma unroll
        for (int nt = 0; nt < 4; nt++)
            #pragma unroll
            for (int j = 0; j < 4; j++) acc[mt][nt][j] = 0.f;

    const int aR = tid >> 2;            // 0..63
    const int aK = (tid & 3) * 4;       // 0,4,8,12
    const int bR = tid >> 4;            // 0..15
    const int bC = (tid & 15) * 4;      // 0..60

    for (int k0 = 0; k0 < K; k0 += 16) {
        // load + split A tile (128x16) : 2 float4 per thread
        #pragma unroll
        for (int it = 0; it < 2; it++) {
            int row = aR + it * 64;
            int gr = rowBase + row;
            float4 v = make_float4(0.f, 0.f, 0.f, 0.f);
            if (gr < N) v = *(const float4*)&A[(size_t)gr * K + k0 + aK];
            float vv[4] = {v.x, v.y, v.z, v.w};
            #pragma unroll
            for (int j = 0; j < 4; j++) {
                uint32_t h, l;
                tf32_split(vv[j], h, l);
                As_hi[row * AS_STRIDE + aK + j] = __uint_as_float(h);
                As_lo[row * AS_STRIDE + aK + j] = __uint_as_float(l);
            }
        }
        // load + split B tile (16x64): 1 float4 per thread
        {
            float4 v = *(const float4*)&W[(size_t)(k0 + bR) * M + colBase + bC];
            float vv[4] = {v.x, v.y, v.z, v.w};
            #pragma unroll
            for (int j = 0; j < 4; j++) {
                uint32_t h, l;
                tf32_split(vv[j], h, l);
                Bs_hi[bR * BS_STRIDE + bC + j] = __uint_as_float(h);
                Bs_lo[bR * BS_STRIDE + bC + j] = __uint_as_float(l);
            }
        }
        __syncthreads();

        #pragma unroll
        for (int ks = 0; ks < 2; ks++) {
            const int kb = ks * 8;
            uint32_t ahi[2][4], alo[2][4];
            #pragma unroll
            for (int mt = 0; mt < 2; mt++) {
                int r0 = warpM * 32 + mt * 16 + gid;
                ahi[mt][0] = __float_as_uint(As_hi[r0 * AS_STRIDE + kb + tig]);
                ahi[mt][1] = __float_as_uint(As_hi[(r0 + 8) * AS_STRIDE + kb + tig]);
                ahi[mt][2] = __float_as_uint(As_hi[r0 * AS_STRIDE + kb + tig + 4]);
                ahi[mt][3] = __float_as_uint(As_hi[(r0 + 8) * AS_STRIDE + kb + tig + 4]);
                alo[mt][0] = __float_as_uint(As_lo[r0 * AS_STRIDE + kb + tig]);
                alo[mt][1] = __float_as_uint(As_lo[(r0 + 8) * AS_STRIDE + kb + tig]);
                alo[mt][2] = __float_as_uint(As_lo[r0 * AS_STRIDE + kb + tig + 4]);
                alo[mt][3] = __float_as_uint(As_lo[(r0 + 8) * AS_STRIDE + kb + tig + 4]);
            }
            uint32_t bhi[4][2], blo[4][2];
            #pragma unroll
            for (int nt = 0; nt < 4; nt++) {
                int c0 = warpN * 32 + nt * 8 + gid;
                bhi[nt][0] = __float_as_uint(Bs_hi[(kb + tig) * BS_STRIDE + c0]);
                bhi[nt][1] = __float_as_uint(Bs_hi[(kb + tig + 4) * BS_STRIDE + c0]);
                blo[nt][0] = __float_as_uint(Bs_lo[(kb + tig) * BS_STRIDE + c0]);
                blo[nt][1] = __float_as_uint(Bs_lo[(kb + tig + 4) * BS_STRIDE + c0]);
            }
            #pragma unroll
            for (int mt = 0; mt < 2; mt++)
                #pragma unroll
                for (int nt = 0; nt < 4; nt++) {
                    mma_tf32(acc[mt][nt], ahi[mt][0], ahi[mt][1], ahi[mt][2], ahi[mt][3],
                             bhi[nt][0], bhi[nt][1]);
                    mma_tf32(acc[mt][nt], ahi[mt][0], ahi[mt][1], ahi[mt][2], ahi[mt][3],
                             blo[nt][0], blo[nt][1]);
                    mma_tf32(acc[mt][nt], alo[mt][0], alo[mt][1], alo[mt][2], alo[mt][3],
                             bhi[nt][0], bhi[nt][1]);
                }
        }
        __syncthreads();
    }

    // epilogue
    #pragma unroll
    for (int mt = 0; mt < 2; mt++) {
        int r0 = rowBase + warpM * 32 + mt * 16 + gid;
        #pragma unroll
        for (int nt = 0; nt < 4; nt++) {
            int col = colBase + warpN * 32 + nt * 8 + 2 * tig;
            float* c = acc[mt][nt];
            if (EPI == 0) {
                float b0 = bias[col], b1 = bias[col + 1];
                if (r0 < N) {
                    float2 o = make_float2(fmaxf(c[0] + b0, 0.f), fmaxf(c[1] + b1, 0.f));
                    *(float2*)&out[(size_t)r0 * M + col] = o;
                }
                if (r0 + 8 < N) {
                    float2 o = make_float2(fmaxf(c[2] + b0, 0.f), fmaxf(c[3] + b1, 0.f));
                    *(float2*)&out[(size_t)(r0 + 8) * M + col] = o;
                }
            } else {
                if (r0 < N) {
                    float d = g_dinv[r0];
                    float2 o = make_float2(c[0] * d, c[1] * d);
                    *(float2*)&out[(size_t)r0 * M + col] = o;
                }
                if (r0 + 8 < N) {
                    float d = g_dinv[r0 + 8];
                    float2 o = make_float2(c[2] * d, c[3] * d);
                    *(float2*)&out[(size_t)(r0 + 8) * M + col] = o;
                }
            }
        }
    }
}

// ---------------- small GEMM (K=128, M=2): warp per row, dinv epilogue ----------------
__global__ __launch_bounds__(256) void k_gemm3(const float* __restrict__ A,
                                               const float* __restrict__ W3,
                                               float* __restrict__ out) {
    __shared__ float w[256];
    int tid = threadIdx.x;
    w[tid] = W3[tid];
    __syncthreads();
    int warp = (blockIdx.x * blockDim.x + tid) >> 5;
    int lane = tid & 31;
    if (warp >= N_NODES) return;
    float4 h = *(const float4*)&A[(size_t)warp * 128 + lane * 4];
    float hv[4] = {h.x, h.y, h.z, h.w};
    float a0 = 0.f, a1 = 0.f;
    #pragma unroll
    for (int j = 0; j < 4; j++) {
        int k = lane * 4 + j;
        a0 += hv[j] * w[k * 2 + 0];
        a1 += hv[j] * w[k * 2 + 1];
    }
    #pragma unroll
    for (int off = 16; off; off >>= 1) {
        a0 += __shfl_down_sync(0xFFFFFFFFu, a0, off);
        a1 += __shfl_down_sync(0xFFFFFFFFu, a1, off);
    }
    if (lane == 0) {
        float s = g_dinv[warp];
        out[(size_t)warp * 2 + 0] = a0 * s;
        out[(size_t)warp * 2 + 1] = a1 * s;
    }
}

// ---------------- aggregation: warp per node, gather from CSR ----------------
// out_i = [relu]( dinv_i * (sum_{src in(i)} hs[src] + hs[i]) [+ bias] )
template <int CH, bool BIAS, bool RELU>
__global__ __launch_bounds__(256) void k_agg(const float* __restrict__ hs,
                                             const float* __restrict__ bias,
                                             float* __restrict__ out) {
    constexpr int V = CH / 128;
    int warp = (blockIdx.x * blockDim.x + threadIdx.x) >> 5;
    int lane = threadIdx.x & 31;
    if (warp >= N_NODES) return;

    float4 acc[V];
    #pragma unroll
    for (int v = 0; v < V; v++)
        acc[v] = *(const float4*)&hs[(size_t)warp * CH + v * 128 + lane * 4];

    int e = g_rowptr[warp], eEnd = g_rowptr[warp + 1];
    for (; e + 1 < eEnd; e += 2) {
        int s0 = g_col[e], s1 = g_col[e + 1];
        #pragma unroll
        for (int v = 0; v < V; v++) {
            float4 x0 = *(const float4*)&hs[(size_t)s0 * CH + v * 128 + lane * 4];
            float4 x1 = *(const float4*)&hs[(size_t)s1 * CH + v * 128 + lane * 4];
            acc[v].x += x0.x + x1.x;
            acc[v].y += x0.y + x1.y;
            acc[v].z += x0.z + x1.z;
            acc[v].w += x0.w + x1.w;
        }
    }
    if (e < eEnd) {
        int s0 = g_col[e];
        #pragma unroll
        for (int v = 0; v < V; v++) {
            float4 x0 = *(const float4*)&hs[(size_t)s0 * CH + v * 128 + lane * 4];
            acc[v].x += x0.x;
            acc[v].y += x0.y;
            acc[v].z += x0.z;
            acc[v].w += x0.w;
        }
    }

    float d = g_dinv[warp];
    #pragma unroll
    for (int v = 0; v < V; v++) {
        int c = v * 128 + lane * 4;
        float4 o;
        o.x = acc[v].x * d;
        o.y = acc[v].y * d;
        o.z = acc[v].z * d;
        o.w = acc[v].w * d;
        if (BIAS) {
            float4 b = *(const float4*)&bias[c];
            o.x += b.x; o.y += b.y; o.z += b.z; o.w += b.w;
        }
        if (RELU) {
            o.x = fmaxf(o.x, 0.f); o.y = fmaxf(o.y, 0.f);
            o.z = fmaxf(o.z, 0.f); o.w = fmaxf(o.w, 0.f);
        }
        *(float4*)&out[(size_t)warp * CH + c] = o;
    }
}

// ---------------- final aggregation + log_softmax (CH=2) ----------------
__global__ __launch_bounds__(256) void k_agg3(const float* __restrict__ b3,
                                              float* __restrict__ out) {
    int i = blockIdx.x * blockDim.x + threadIdx.x;
    if (i >= N_NODES) return;
    float2 acc = *(const float2*)&g_hs3[(size_t)i * 2];
    int e = g_rowptr[i], eE = g_rowptr[i + 1];
    for (; e < eE; e++) {
        int s = g_col[e];
        float2 x = *(const float2*)&g_hs3[(size_t)s * 2];
        acc.x += x.x;
        acc.y += x.y;
    }
    float d = g_dinv[i];
    float v0 = acc.x * d + b3[0];
    float v1 = acc.y * d + b3[1];
    float m = fmaxf(v0, v1);
    float lse = m + logf(expf(v0 - m) + expf(v1 - m));
    out[(size_t)i * 2 + 0] = v0 - lse;
    out[(size_t)i * 2 + 1] = v1 - lse;
}

// ---------------- launch ----------------
extern "C" void kernel_launch(void* const* d_in, const int* in_sizes, int n_in,
                              void* d_out, int out_size) {
    const float* x  = (const float*)d_in[0];
    const float* W1 = (const float*)d_in[1];
    const float* b1 = (const float*)d_in[2];
    const float* W2 = (const float*)d_in[3];
    const float* b2 = (const float*)d_in[4];
    const float* W3 = (const float*)d_in[5];
    const float* b3 = (const float*)d_in[6];
    const int* ei   = (const int*)d_in[7];   // int32 (JAX x64 disabled)
    const int* src  = ei;
    const int* dst  = ei + N_EDGES;
    float* out = (float*)d_out;

    float *bufA, *bufB, *hs3;
    cudaGetSymbolAddress((void**)&bufA, g_bufA);
    cudaGetSymbolAddress((void**)&bufB, g_bufB);
    cudaGetSymbolAddress((void**)&hs3, g_hs3);

    const int TB = 256;
    // graph build
    k_zero_counts<<<(N_NODES + TB - 1) / TB, TB>>>();
    k_count<<<(N_EDGES + TB - 1) / TB, TB>>>(dst);
    k_scan1<<<SCAN_BLKS, TB>>>();
    k_scan2<<<1, TB>>>();
    k_scan3<<<SCAN_BLKS, TB>>>();
    k_fill<<<(N_EDGES + TB - 1) / TB, TB>>>(src, dst);

    int gemmRows = (N_NODES + 127) / 128;
    int aggBlocks = (N_NODES * 32 + TB - 1) / TB;

    // xs = dinv (.) x  -> bufA
    k_scale<<<(N_NODES * 32 + TB - 1) / TB, TB>>>(x, bufA);
    // ax = dinv_i*(sum xs + self) -> bufB  [N,128]
    k_agg<IN_CH, false, false><<<aggBlocks, TB>>>(bufA, nullptr, bufB);
    // h1 = relu(ax @ W1 + b1) -> bufA  [N,256]
    k_gemm_tf32<0><<<dim3(gemmRows, HID1 / 64), TB>>>(bufB, W1, b1, bufA, N_NODES, IN_CH, HID1);
    // hs2 = dinv (.) (h1 @ W2) -> bufB  [N,128]
    k_gemm_tf32<1><<<dim3(gemmRows, HID2 / 64), TB>>>(bufA, W2, nullptr, bufB, N_NODES, HID1, HID2);
    // h2 = relu(dinv_i*(sum hs2 + self) + b2) -> bufA  [N,128]
    k_agg<HID2, true, true><<<aggBlocks, TB>>>(bufB, b2, bufA);
    // hs3 = dinv (.) (h2 @ W3) -> g_hs3  [N,2]
    k_gemm3<<<aggBlocks, TB>>>(bufA, W3, hs3);
    // out = log_softmax(agg3 + b3)
    k_agg3<<<(N_NODES + TB - 1) / TB, TB>>>(b3, out);
}

// round 4
// speedup vs baseline: 1.7028x; 1.2622x over previous
#include <cuda_runtime.h>
#include <cuda_bf16.h>
#include <math.h>
#include <stdint.h>

#define N_NODES 50000
#define N_EDGES 600000
#define IN_CH   128
#define HID1    256
#define HID2    128
#define SCAN_BLKS 196   // ceil(50000/256)

// ---------------- device scratch ----------------
__device__ int   g_counts[N_NODES];
__device__ int   g_rowptr[N_NODES + 1];
__device__ int   g_cursor[N_NODES];
__device__ float g_dinv[N_NODES];
__device__ int   g_col[N_EDGES];
__device__ int   g_bsum[SCAN_BLKS];
__device__ int   g_boff[SCAN_BLKS];
__device__ float g_bufA[(size_t)N_NODES * 256];
__device__ float g_bufB[(size_t)N_NODES * 256];
__device__ float g_hs3[(size_t)N_NODES * 2];

// ---------------- graph construction ----------------
__global__ void k_zero_counts() {
    int i = blockIdx.x * blockDim.x + threadIdx.x;
    if (i < N_NODES) g_counts[i] = 0;
}

__global__ void k_count(const int* __restrict__ dst) {
    int e = blockIdx.x * blockDim.x + threadIdx.x;
    if (e < N_EDGES) atomicAdd(&g_counts[dst[e]], 1);
}

__global__ __launch_bounds__(256) void k_scan1() {
    __shared__ int sh[256];
    int b = blockIdx.x, t = threadIdx.x;
    int i = b * 256 + t;
    int v = (i < N_NODES) ? g_counts[i] : 0;
    sh[t] = v;
    __syncthreads();
    #pragma unroll
    for (int off = 1; off < 256; off <<= 1) {
        int u = (t >= off) ? sh[t - off] : 0;
        __syncthreads();
        sh[t] += u;
        __syncthreads();
    }
    if (i < N_NODES) g_rowptr[i + 1] = sh[t];
    if (t == 255) g_bsum[b] = sh[255];
}

__global__ __launch_bounds__(256) void k_scan2() {
    __shared__ int sh[256];
    int t = threadIdx.x;
    int v = (t < SCAN_BLKS) ? g_bsum[t] : 0;
    sh[t] = v;
    __syncthreads();
    #pragma unroll
    for (int off = 1; off < 256; off <<= 1) {
        int u = (t >= off) ? sh[t - off] : 0;
        __syncthreads();
        sh[t] += u;
        __syncthreads();
    }
    if (t < SCAN_BLKS) g_boff[t] = sh[t] - v;  // exclusive
}

__global__ __launch_bounds__(256) void k_scan3() {
    int b = blockIdx.x, t = threadIdx.x;
    int i = b * 256 + t;
    if (i < N_NODES) {
        int rp1 = g_rowptr[i + 1] + g_boff[b];
        g_rowptr[i + 1] = rp1;
        int c = g_counts[i];
        g_cursor[i] = rp1 - c;
        g_dinv[i] = rsqrtf((float)(c + 1));
    }
    if (i == 0) g_rowptr[0] = 0;
}

__global__ void k_fill(const int* __restrict__ src,
                       const int* __restrict__ dst) {
    int e = blockIdx.x * blockDim.x + threadIdx.x;
    if (e < N_EDGES) {
        int d = dst[e];
        int pos = atomicAdd(&g_cursor[d], 1);
        g_col[pos] = src[e];
    }
}

// ---------------- bf16 split helpers + mma ----------------
// pack two consecutive-K fp32 into (hi, lo) bf16x2 pairs
__device__ __forceinline__ void bf16_split2(float a, float b, uint32_t& hi, uint32_t& lo) {
    __nv_bfloat162 h = __floats2bfloat162_rn(a, b);
    hi = *(uint32_t*)&h;
    float ra = a - __bfloat162float(h.x);
    float rb = b - __bfloat162float(h.y);
    __nv_bfloat162 l = __floats2bfloat162_rn(ra, rb);
    lo = *(uint32_t*)&l;
}

__device__ __forceinline__ void mma_bf16(float* c, uint32_t a0, uint32_t a1,
                                         uint32_t a2, uint32_t a3,
                                         uint32_t b0, uint32_t b1) {
    asm volatile(
        "mma.sync.aligned.m16n8k16.row.col.f32.bf16.bf16.f32 "
        "{%0,%1,%2,%3}, {%4,%5,%6,%7}, {%8,%9}, {%0,%1,%2,%3};"
        : "+f"(c[0]), "+f"(c[1]), "+f"(c[2]), "+f"(c[3])
        : "r"(a0), "r"(a1), "r"(a2), "r"(a3), "r"(b0), "r"(b1));
}

// ---------------- 3xBF16 GEMM: out[N,M] = A[N,K] @ W[K,M] (+epilogue) ----------------
// BM=128, BN=128, BK=32; 8 warps: warpM 4 (32 rows, 2 m-tiles) x warpN 2 (64 cols, 8 n-tiles)
// EPI 0: out = relu(acc + bias[col]);  EPI 1: out = dinv[row] * acc
#define KP 16           // K-pairs per BK (32/2)
#define TS 17           // padded stride in uint32
template <int EPI>
__global__ __launch_bounds__(256) void k_gemm_bf16(const float* __restrict__ A,
                                                   const float* __restrict__ W,
                                                   const float* __restrict__ bias,
                                                   float* __restrict__ out,
                                                   int N, int K, int M) {
    __shared__ uint32_t As_hi[128 * TS];
    __shared__ uint32_t As_lo[128 * TS];
    __shared__ uint32_t Bs_hi[128 * TS];
    __shared__ uint32_t Bs_lo[128 * TS];

    const int tid  = threadIdx.x;
    const int lane = tid & 31;
    const int warp = tid >> 5;
    const int gid  = lane >> 2;     // 0..7
    const int tig  = lane & 3;      // 0..3
    const int warpM = warp & 3;     // 0..3 -> rows warpM*32
    const int warpN = warp >> 2;    // 0..1 -> cols warpN*64
    const int rowBase = blockIdx.x * 128;
    const int colBase = blockIdx.y * 128;

    float acc[2][8][4];
    #pragma unroll
    for (int mt = 0; mt < 2; mt++)
        #pragma unroll
        for (int nt = 0; nt < 8; nt++)
            #pragma unroll
            for (int j = 0; j < 4; j++) acc[mt][nt][j] = 0.f;

    // A load mapping: row = tid>>1 (0..127), 16 floats starting at (tid&1)*16
    const int aRow = tid >> 1;
    const int aCol = (tid & 1) * 16;
    // B load mapping: m = tid&127, k2 block = (tid>>7)*8 + j
    const int bM = tid & 127;
    const int bK2base = (tid >> 7) * 8;

    for (int k0 = 0; k0 < K; k0 += 32) {
        // --- A tile 128x32 -> split bf16 pairs ---
        {
            int gr = rowBase + aRow;
            float v[16];
            if (gr < N) {
                #pragma unroll
                for (int q = 0; q < 4; q++) {
                    float4 f = *(const float4*)&A[(size_t)gr * K + k0 + aCol + q * 4];
                    v[q * 4 + 0] = f.x; v[q * 4 + 1] = f.y;
                    v[q * 4 + 2] = f.z; v[q * 4 + 3] = f.w;
                }
            } else {
                #pragma unroll
                for (int q = 0; q < 16; q++) v[q] = 0.f;
            }
            #pragma unroll
            for (int j = 0; j < 8; j++) {
                uint32_t h, l;
                bf16_split2(v[2 * j], v[2 * j + 1], h, l);
                int k2 = aCol / 2 + j;
                As_hi[aRow * TS + k2] = h;
                As_lo[aRow * TS + k2] = l;
            }
        }
        // --- B tile 32x128 -> transpose + split into [m][k2] ---
        #pragma unroll
        for (int j = 0; j < 8; j++) {
            int k2 = bK2base + j;
            int k = k0 + 2 * k2;
            float w0 = W[(size_t)k * M + colBase + bM];
            float w1 = W[(size_t)(k + 1) * M + colBase + bM];
            uint32_t h, l;
            bf16_split2(w0, w1, h, l);
            Bs_hi[bM * TS + k2] = h;
            Bs_lo[bM * TS + k2] = l;
        }
        __syncthreads();

        #pragma unroll
        for (int ks = 0; ks < 2; ks++) {
            const int kb = ks * 8;
            uint32_t ahi[2][4], alo[2][4];
            #pragma unroll
            for (int mt = 0; mt < 2; mt++) {
                int r0 = warpM * 32 + mt * 16 + gid;
                ahi[mt][0] = As_hi[r0 * TS + kb + tig];
                ahi[mt][1] = As_hi[(r0 + 8) * TS + kb + tig];
                ahi[mt][2] = As_hi[r0 * TS + kb + tig + 4];
                ahi[mt][3] = As_hi[(r0 + 8) * TS + kb + tig + 4];
                alo[mt][0] = As_lo[r0 * TS + kb + tig];
                alo[mt][1] = As_lo[(r0 + 8) * TS + kb + tig];
                alo[mt][2] = As_lo[r0 * TS + kb + tig + 4];
                alo[mt][3] = As_lo[(r0 + 8) * TS + kb + tig + 4];
            }
            uint32_t bhi[8][2], blo[8][2];
            #pragma unroll
            for (int nt = 0; nt < 8; nt++) {
                int c0 = warpN * 64 + nt * 8 + gid;
                bhi[nt][0] = Bs_hi[c0 * TS + kb + tig];
                bhi[nt][1] = Bs_hi[c0 * TS + kb + tig + 4];
                blo[nt][0] = Bs_lo[c0 * TS + kb + tig];
                blo[nt][1] = Bs_lo[c0 * TS + kb + tig + 4];
            }
            #pragma unroll
            for (int mt = 0; mt < 2; mt++)
                #pragma unroll
                for (int nt = 0; nt < 8; nt++) {
                    mma_bf16(acc[mt][nt], ahi[mt][0], ahi[mt][1], ahi[mt][2], ahi[mt][3],
                             bhi[nt][0], bhi[nt][1]);
                    mma_bf16(acc[mt][nt], ahi[mt][0], ahi[mt][1], ahi[mt][2], ahi[mt][3],
                             blo[nt][0], blo[nt][1]);
                    mma_bf16(acc[mt][nt], alo[mt][0], alo[mt][1], alo[mt][2], alo[mt][3],
                             bhi[nt][0], bhi[nt][1]);
                }
        }
        __syncthreads();
    }

    // epilogue
    #pragma unroll
    for (int mt = 0; mt < 2; mt++) {
        int r0 = rowBase + warpM * 32 + mt * 16 + gid;
        #pragma unroll
        for (int nt = 0; nt < 8; nt++) {
            int col = colBase + warpN * 64 + nt * 8 + 2 * tig;
            float* c = acc[mt][nt];
            if (EPI == 0) {
                float b0 = bias[col], b1 = bias[col + 1];
                if (r0 < N) {
                    float2 o = make_float2(fmaxf(c[0] + b0, 0.f), fmaxf(c[1] + b1, 0.f));
                    *(float2*)&out[(size_t)r0 * M + col] = o;
                }
                if (r0 + 8 < N) {
                    float2 o = make_float2(fmaxf(c[2] + b0, 0.f), fmaxf(c[3] + b1, 0.f));
                    *(float2*)&out[(size_t)(r0 + 8) * M + col] = o;
                }
            } else {
                if (r0 < N) {
                    float d = g_dinv[r0];
                    float2 o = make_float2(c[0] * d, c[1] * d);
                    *(float2*)&out[(size_t)r0 * M + col] = o;
                }
                if (r0 + 8 < N) {
                    float d = g_dinv[r0 + 8];
                    float2 o = make_float2(c[2] * d, c[3] * d);
                    *(float2*)&out[(size_t)(r0 + 8) * M + col] = o;
                }
            }
        }
    }
}

// ---------------- small GEMM (K=128, M=2): warp per row, dinv epilogue ----------------
__global__ __launch_bounds__(256) void k_gemm3(const float* __restrict__ A,
                                               const float* __restrict__ W3,
                                               float* __restrict__ out) {
    __shared__ float w[256];
    int tid = threadIdx.x;
    w[tid] = W3[tid];
    __syncthreads();
    int warp = (blockIdx.x * blockDim.x + tid) >> 5;
    int lane = tid & 31;
    if (warp >= N_NODES) return;
    float4 h = *(const float4*)&A[(size_t)warp * 128 + lane * 4];
    float hv[4] = {h.x, h.y, h.z, h.w};
    float a0 = 0.f, a1 = 0.f;
    #pragma unroll
    for (int j = 0; j < 4; j++) {
        int k = lane * 4 + j;
        a0 += hv[j] * w[k * 2 + 0];
        a1 += hv[j] * w[k * 2 + 1];
    }
    #pragma unroll
    for (int off = 16; off; off >>= 1) {
        a0 += __shfl_down_sync(0xFFFFFFFFu, a0, off);
        a1 += __shfl_down_sync(0xFFFFFFFFu, a1, off);
    }
    if (lane == 0) {
        float s = g_dinv[warp];
        out[(size_t)warp * 2 + 0] = a0 * s;
        out[(size_t)warp * 2 + 1] = a1 * s;
    }
}

// ---------------- aggregation: warp per node, gather from CSR ----------------
// SRC_SCALE: message = dinv[s]*hs[s] (fold per-source norm; for layer 0 on raw x)
// out_i = [relu]( dinv_i * (sum msg + self) [+ bias] )
template <int CH, bool BIAS, bool RELU, bool SRC_SCALE>
__global__ __launch_bounds__(256) void k_agg(const float* __restrict__ hs,
                                             const float* __restrict__ bias,
                                             float* __restrict__ out) {
    constexpr int V = CH / 128;
    int warp = (blockIdx.x * blockDim.x + threadIdx.x) >> 5;
    int lane = threadIdx.x & 31;
    if (warp >= N_NODES) return;

    float dself = g_dinv[warp];
    float4 acc[V];
    #pragma unroll
    for (int v = 0; v < V; v++) {
        acc[v] = *(const float4*)&hs[(size_t)warp * CH + v * 128 + lane * 4];
        if (SRC_SCALE) {
            acc[v].x *= dself; acc[v].y *= dself;
            acc[v].z *= dself; acc[v].w *= dself;
        }
    }

    int e = g_rowptr[warp], eEnd = g_rowptr[warp + 1];
    for (; e + 1 < eEnd; e += 2) {
        int s0 = g_col[e], s1 = g_col[e + 1];
        float d0 = SRC_SCALE ? g_dinv[s0] : 1.f;
        float d1 = SRC_SCALE ? g_dinv[s1] : 1.f;
        #pragma unroll
        for (int v = 0; v < V; v++) {
            float4 x0 = *(const float4*)&hs[(size_t)s0 * CH + v * 128 + lane * 4];
            float4 x1 = *(const float4*)&hs[(size_t)s1 * CH + v * 128 + lane * 4];
            if (SRC_SCALE) {
                acc[v].x += x0.x * d0 + x1.x * d1;
                acc[v].y += x0.y * d0 + x1.y * d1;
                acc[v].z += x0.z * d0 + x1.z * d1;
                acc[v].w += x0.w * d0 + x1.w * d1;
            } else {
                acc[v].x += x0.x + x1.x;
                acc[v].y += x0.y + x1.y;
                acc[v].z += x0.z + x1.z;
                acc[v].w += x0.w + x1.w;
            }
        }
    }
    if (e < eEnd) {
        int s0 = g_col[e];
        float d0 = SRC_SCALE ? g_dinv[s0] : 1.f;
        #pragma unroll
        for (int v = 0; v < V; v++) {
            float4 x0 = *(const float4*)&hs[(size_t)s0 * CH + v * 128 + lane * 4];
            if (SRC_SCALE) {
                acc[v].x += x0.x * d0; acc[v].y += x0.y * d0;
                acc[v].z += x0.z * d0; acc[v].w += x0.w * d0;
            } else {
                acc[v].x += x0.x; acc[v].y += x0.y;
                acc[v].z += x0.z; acc[v].w += x0.w;
            }
        }
    }

    #pragma unroll
    for (int v = 0; v < V; v++) {
        int c = v * 128 + lane * 4;
        float4 o;
        o.x = acc[v].x * dself;
        o.y = acc[v].y * dself;
        o.z = acc[v].z * dself;
        o.w = acc[v].w * dself;
        if (BIAS) {
            float4 b = *(const float4*)&bias[c];
            o.x += b.x; o.y += b.y; o.z += b.z; o.w += b.w;
        }
        if (RELU) {
            o.x = fmaxf(o.x, 0.f); o.y = fmaxf(o.y, 0.f);
            o.z = fmaxf(o.z, 0.f); o.w = fmaxf(o.w, 0.f);
        }
        *(float4*)&out[(size_t)warp * CH + c] = o;
    }
}

// ---------------- final aggregation + log_softmax (CH=2) ----------------
__global__ __launch_bounds__(256) void k_agg3(const float* __restrict__ b3,
                                              float* __restrict__ out) {
    int i = blockIdx.x * blockDim.x + threadIdx.x;
    if (i >= N_NODES) return;
    float2 acc = *(const float2*)&g_hs3[(size_t)i * 2];
    int e = g_rowptr[i], eE = g_rowptr[i + 1];
    for (; e < eE; e++) {
        int s = g_col[e];
        float2 x = *(const float2*)&g_hs3[(size_t)s * 2];
        acc.x += x.x;
        acc.y += x.y;
    }
    float d = g_dinv[i];
    float v0 = acc.x * d + b3[0];
    float v1 = acc.y * d + b3[1];
    float m = fmaxf(v0, v1);
    float lse = m + logf(expf(v0 - m) + expf(v1 - m));
    out[(size_t)i * 2 + 0] = v0 - lse;
    out[(size_t)i * 2 + 1] = v1 - lse;
}

// ---------------- launch ----------------
extern "C" void kernel_launch(void* const* d_in, const int* in_sizes, int n_in,
                              void* d_out, int out_size) {
    const float* x  = (const float*)d_in[0];
    const float* W1 = (const float*)d_in[1];
    const float* b1 = (const float*)d_in[2];
    const float* W2 = (const float*)d_in[3];
    const float* b2 = (const float*)d_in[4];
    const float* W3 = (const float*)d_in[5];
    const float* b3 = (const float*)d_in[6];
    const int* ei   = (const int*)d_in[7];   // int32 (JAX x64 disabled)
    const int* src  = ei;
    const int* dst  = ei + N_EDGES;
    float* out = (float*)d_out;

    float *bufA, *bufB, *hs3;
    cudaGetSymbolAddress((void**)&bufA, g_bufA);
    cudaGetSymbolAddress((void**)&bufB, g_bufB);
    cudaGetSymbolAddress((void**)&hs3, g_hs3);

    const int TB = 256;
    // graph build
    k_zero_counts<<<(N_NODES + TB - 1) / TB, TB>>>();
    k_count<<<(N_EDGES + TB - 1) / TB, TB>>>(dst);
    k_scan1<<<SCAN_BLKS, TB>>>();
    k_scan2<<<1, TB>>>();
    k_scan3<<<SCAN_BLKS, TB>>>();
    k_fill<<<(N_EDGES + TB - 1) / TB, TB>>>(src, dst);

    int gemmRows = (N_NODES + 127) / 128;
    int aggBlocks = (N_NODES * 32 + TB - 1) / TB;

    // ax_i = dinv_i*(sum dinv_s*x_s + dinv_i*x_i) -> bufB  [N,128]
    k_agg<IN_CH, false, false, true><<<aggBlocks, TB>>>(x, nullptr, bufB);
    // h1 = relu(ax @ W1 + b1) -> bufA  [N,256]
    k_gemm_bf16<0><<<dim3(gemmRows, HID1 / 128), TB>>>(bufB, W1, b1, bufA, N_NODES, IN_CH, HID1);
    // hs2 = dinv (.) (h1 @ W2) -> bufB  [N,128]
    k_gemm_bf16<1><<<dim3(gemmRows, HID2 / 128), TB>>>(bufA, W2, nullptr, bufB, N_NODES, HID1, HID2);
    // h2 = relu(dinv_i*(sum hs2 + self) + b2) -> bufA  [N,128]
    k_agg<HID2, true, true, false><<<aggBlocks, TB>>>(bufB, b2, bufA);
    // hs3 = dinv (.) (h2 @ W3) -> g_hs3  [N,2]
    k_gemm3<<<aggBlocks, TB>>>(bufA, W3, hs3);
    // out = log_softmax(agg3 + b3)
    k_agg3<<<(N_NODES + TB - 1) / TB, TB>>>(b3, out);
}

// round 5
// speedup vs baseline: 1.8957x; 1.1133x over previous
#include <cuda_runtime.h>
#include <cuda_bf16.h>
#include <math.h>
#include <stdint.h>

#define N_NODES 50000
#define N_EDGES 600000
#define N_PAD   50048   // 391*128
#define IN_CH   128
#define HID1    256
#define HID2    128
#define SCAN_BLKS 196   // ceil(50000/256)

// ---------------- device scratch ----------------
__device__ int   g_counts[N_NODES];
__device__ int   g_rowptr[N_NODES + 1];
__device__ int   g_cursor[N_NODES];
__device__ float g_dinv[N_NODES];
__device__ int   g_col[N_EDGES];
__device__ int   g_bsum[SCAN_BLKS];
__device__ int   g_boff[SCAN_BLKS];

__device__ __align__(16) __nv_bfloat16 g_a0_hi[(size_t)N_PAD * 128];
__device__ __align__(16) __nv_bfloat16 g_a0_lo[(size_t)N_PAD * 128];
__device__ __align__(16) __nv_bfloat16 g_h1_hi[(size_t)N_PAD * 256];
__device__ __align__(16) __nv_bfloat16 g_h1_lo[(size_t)N_PAD * 256];
__device__ __align__(16) __nv_bfloat16 g_wt1_hi[256 * 128];
__device__ __align__(16) __nv_bfloat16 g_wt1_lo[256 * 128];
__device__ __align__(16) __nv_bfloat16 g_wt2_hi[128 * 256];
__device__ __align__(16) __nv_bfloat16 g_wt2_lo[128 * 256];
__device__ float g_hs2[(size_t)N_NODES * 128];
__device__ float g_hs3[(size_t)N_NODES * 2];

// ---------------- graph construction ----------------
__global__ void k_zero_counts() {
    int i = blockIdx.x * blockDim.x + threadIdx.x;
    if (i < N_NODES) g_counts[i] = 0;
}

__global__ void k_count(const int* __restrict__ dst) {
    int e = blockIdx.x * blockDim.x + threadIdx.x;
    if (e < N_EDGES) atomicAdd(&g_counts[dst[e]], 1);
}

__global__ __launch_bounds__(256) void k_scan1() {
    __shared__ int sh[256];
    int b = blockIdx.x, t = threadIdx.x;
    int i = b * 256 + t;
    int v = (i < N_NODES) ? g_counts[i] : 0;
    sh[t] = v;
    __syncthreads();
    #pragma unroll
    for (int off = 1; off < 256; off <<= 1) {
        int u = (t >= off) ? sh[t - off] : 0;
        __syncthreads();
        sh[t] += u;
        __syncthreads();
    }
    if (i < N_NODES) g_rowptr[i + 1] = sh[t];
    if (t == 255) g_bsum[b] = sh[255];
}

__global__ __launch_bounds__(256) void k_scan2() {
    __shared__ int sh[256];
    int t = threadIdx.x;
    int v = (t < SCAN_BLKS) ? g_bsum[t] : 0;
    sh[t] = v;
    __syncthreads();
    #pragma unroll
    for (int off = 1; off < 256; off <<= 1) {
        int u = (t >= off) ? sh[t - off] : 0;
        __syncthreads();
        sh[t] += u;
        __syncthreads();
    }
    if (t < SCAN_BLKS) g_boff[t] = sh[t] - v;  // exclusive
}

__global__ __launch_bounds__(256) void k_scan3() {
    int b = blockIdx.x, t = threadIdx.x;
    int i = b * 256 + t;
    if (i < N_NODES) {
        int rp1 = g_rowptr[i + 1] + g_boff[b];
        g_rowptr[i + 1] = rp1;
        int c = g_counts[i];
        g_cursor[i] = rp1 - c;
        g_dinv[i] = rsqrtf((float)(c + 1));
    }
    if (i == 0) g_rowptr[0] = 0;
}

__global__ void k_fill(const int* __restrict__ src,
                       const int* __restrict__ dst) {
    int e = blockIdx.x * blockDim.x + threadIdx.x;
    if (e < N_EDGES) {
        int d = dst[e];
        int pos = atomicAdd(&g_cursor[d], 1);
        g_col[pos] = src[e];
    }
}

// ---------------- bf16 split helpers + mma ----------------
__device__ __forceinline__ void bf16_split2(float a, float b, uint32_t& hi, uint32_t& lo) {
    __nv_bfloat162 h = __floats2bfloat162_rn(a, b);
    hi = *(uint32_t*)&h;
    float ra = a - __bfloat162float(h.x);
    float rb = b - __bfloat162float(h.y);
    __nv_bfloat162 l = __floats2bfloat162_rn(ra, rb);
    lo = *(uint32_t*)&l;
}

__device__ __forceinline__ void mma_bf16(float* c, uint32_t a0, uint32_t a1,
                                         uint32_t a2, uint32_t a3,
                                         uint32_t b0, uint32_t b1) {
    asm volatile(
        "mma.sync.aligned.m16n8k16.row.col.f32.bf16.bf16.f32 "
        "{%0,%1,%2,%3}, {%4,%5,%6,%7}, {%8,%9}, {%0,%1,%2,%3};"
        : "+f"(c[0]), "+f"(c[1]), "+f"(c[2]), "+f"(c[3])
        : "r"(a0), "r"(a1), "r"(a2), "r"(a3), "r"(b0), "r"(b1));
}

__device__ __forceinline__ void cp16(uint32_t saddr, const void* gptr) {
    asm volatile("cp.async.ca.shared.global [%0], [%1], 16;" :: "r"(saddr), "l"(gptr));
}

// ---------------- weight prep: split + transpose W1, W2 into bf16 planes ----------------
__global__ __launch_bounds__(256) void k_split_w(const float* __restrict__ W1,
                                                 const float* __restrict__ W2) {
    int idx = blockIdx.x * blockDim.x + threadIdx.x;
    if (idx < 128 * 256) {
        int k = idx >> 8, m = idx & 255;          // W1[k][m], K=128, M=256
        float v = W1[idx];
        __nv_bfloat16 h = __float2bfloat16_rn(v);
        __nv_bfloat16 l = __float2bfloat16_rn(v - __bfloat162float(h));
        g_wt1_hi[m * 128 + k] = h;
        g_wt1_lo[m * 128 + k] = l;
    } else {
        int j = idx - 128 * 256;
        int k = j >> 7, m = j & 127;              // W2[k][m], K=256, M=128
        float v = W2[j];
        __nv_bfloat16 h = __float2bfloat16_rn(v);
        __nv_bfloat16 l = __float2bfloat16_rn(v - __bfloat162float(h));
        g_wt2_hi[m * 256 + k] = h;
        g_wt2_lo[m * 256 + k] = l;
    }
}

// ---------------- 3xBF16 pipelined GEMM ----------------
// BM=128, BN=128, BK=16; smem rows padded to 48B (12 uint32) -> conflict-free
// EPI 0: h = relu(acc + bias[col]) -> split planes out_hi/out_lo
// EPI 1: out_f = dinv[row] * acc   (fp32)
#define RS 12   // row stride in uint32
template <int K, int M, int EPI>
__global__ __launch_bounds__(256, 2) void k_gemm(const __nv_bfloat16* __restrict__ a_hi,
                                                 const __nv_bfloat16* __restrict__ a_lo,
                                                 const __nv_bfloat16* __restrict__ b_hi,
                                                 const __nv_bfloat16* __restrict__ b_lo,
                                                 const float* __restrict__ bias,
                                                 __nv_bfloat16* __restrict__ out_hi,
                                                 __nv_bfloat16* __restrict__ out_lo,
                                                 float* __restrict__ out_f) {
    __shared__ __align__(16) uint32_t smu[2 * 4 * 128 * RS];   // 49152 B

    const int tid  = threadIdx.x;
    const int lane = tid & 31;
    const int warp = tid >> 5;
    const int gid  = lane >> 2;
    const int tig  = lane & 3;
    const int warpM = warp & 3;
    const int warpN = warp >> 2;
    const int rowBase = blockIdx.x * 128;
    const int colBase = blockIdx.y * 128;

    float acc[2][8][4];
    #pragma unroll
    for (int mt = 0; mt < 2; mt++)
        #pragma unroll
        for (int nt = 0; nt < 8; nt++)
            #pragma unroll
            for (int j = 0; j < 4; j++) acc[mt][nt][j] = 0.f;

    const uint32_t sbase = (uint32_t)__cvta_generic_to_shared(smu);
    const int ldRow = tid >> 1;
    const int ldCh  = tid & 1;

    auto load_stage = [&](int s, int k0) {
        size_t ga = (size_t)(rowBase + ldRow) * K + k0 + ldCh * 8;
        size_t gb = (size_t)(colBase + ldRow) * K + k0 + ldCh * 8;
        uint32_t d = sbase + (uint32_t)(((s * 4) * 128 * RS + ldRow * RS + ldCh * 4) * 4);
        cp16(d,                    a_hi + ga);
        cp16(d + 128 * RS * 4,     a_lo + ga);
        cp16(d + 2 * 128 * RS * 4, b_hi + gb);
        cp16(d + 3 * 128 * RS * 4, b_lo + gb);
    };

    constexpr int T = K / 16;
    load_stage(0, 0);
    asm volatile("cp.async.commit_group;");

    #pragma unroll 1
    for (int i = 0; i < T; i++) {
        if (i + 1 < T) load_stage((i + 1) & 1, (i + 1) * 16);
        asm volatile("cp.async.commit_group;");
        asm volatile("cp.async.wait_group 1;");
        __syncthreads();

        const uint32_t* Ah = &smu[((i & 1) * 4 + 0) * 128 * RS];
        const uint32_t* Al = &smu[((i & 1) * 4 + 1) * 128 * RS];
        const uint32_t* Bh = &smu[((i & 1) * 4 + 2) * 128 * RS];
        const uint32_t* Bl = &smu[((i & 1) * 4 + 3) * 128 * RS];

        uint32_t ahi[2][4], alo[2][4];
        #pragma unroll
        for (int mt = 0; mt < 2; mt++) {
            int r0 = warpM * 32 + mt * 16 + gid;
            ahi[mt][0] = Ah[r0 * RS + tig];
            ahi[mt][1] = Ah[(r0 + 8) * RS + tig];
            ahi[mt][2] = Ah[r0 * RS + tig + 4];
            ahi[mt][3] = Ah[(r0 + 8) * RS + tig + 4];
            alo[mt][0] = Al[r0 * RS + tig];
            alo[mt][1] = Al[(r0 + 8) * RS + tig];
            alo[mt][2] = Al[r0 * RS + tig + 4];
            alo[mt][3] = Al[(r0 + 8) * RS + tig + 4];
        }
        #pragma unroll
        for (int nt = 0; nt < 8; nt++) {
            int c0 = warpN * 64 + nt * 8 + gid;
            uint32_t bh0 = Bh[c0 * RS + tig], bh1 = Bh[c0 * RS + tig + 4];
            uint32_t bl0 = Bl[c0 * RS + tig], bl1 = Bl[c0 * RS + tig + 4];
            #pragma unroll
            for (int mt = 0; mt < 2; mt++) {
                mma_bf16(acc[mt][nt], ahi[mt][0], ahi[mt][1], ahi[mt][2], ahi[mt][3], bh0, bh1);
                mma_bf16(acc[mt][nt], ahi[mt][0], ahi[mt][1], ahi[mt][2], ahi[mt][3], bl0, bl1);
                mma_bf16(acc[mt][nt], alo[mt][0], alo[mt][1], alo[mt][2], alo[mt][3], bh0, bh1);
            }
        }
        __syncthreads();
    }

    // epilogue
    #pragma unroll
    for (int mt = 0; mt < 2; mt++) {
        int r0 = rowBase + warpM * 32 + mt * 16 + gid;
        #pragma unroll
        for (int nt = 0; nt < 8; nt++) {
            int col = colBase + warpN * 64 + nt * 8 + 2 * tig;
            float* c = acc[mt][nt];
            if (EPI == 0) {
                float b0 = bias[col], b1 = bias[col + 1];
                if (r0 < N_NODES) {
                    float v0 = fmaxf(c[0] + b0, 0.f), v1 = fmaxf(c[1] + b1, 0.f);
                    uint32_t h, l;
                    bf16_split2(v0, v1, h, l);
                    *(uint32_t*)&out_hi[(size_t)r0 * M + col] = h;
                    *(uint32_t*)&out_lo[(size_t)r0 * M + col] = l;
                }
                if (r0 + 8 < N_NODES) {
                    float v0 = fmaxf(c[2] + b0, 0.f), v1 = fmaxf(c[3] + b1, 0.f);
                    uint32_t h, l;
                    bf16_split2(v0, v1, h, l);
                    *(uint32_t*)&out_hi[(size_t)(r0 + 8) * M + col] = h;
                    *(uint32_t*)&out_lo[(size_t)(r0 + 8) * M + col] = l;
                }
            } else {
                if (r0 < N_NODES) {
                    float d = g_dinv[r0];
                    *(float2*)&out_f[(size_t)r0 * M + col] = make_float2(c[0] * d, c[1] * d);
                }
                if (r0 + 8 < N_NODES) {
                    float d = g_dinv[r0 + 8];
                    *(float2*)&out_f[(size_t)(r0 + 8) * M + col] = make_float2(c[2] * d, c[3] * d);
                }
            }
        }
    }
}

// ---------------- layer-0 aggregation -> split bf16 planes ----------------
// ax_i = dinv_i * (sum_s dinv_s * x_s + dinv_i * x_i)   [N,128] -> hi/lo planes
__global__ __launch_bounds__(256) void k_agg0(const float* __restrict__ x) {
    int node = (blockIdx.x * blockDim.x + threadIdx.x) >> 5;
    int lane = threadIdx.x & 31;
    if (node >= N_NODES) return;

    float dself = g_dinv[node];
    float4 acc = *(const float4*)&x[(size_t)node * 128 + lane * 4];
    acc.x *= dself; acc.y *= dself; acc.z *= dself; acc.w *= dself;

    int e = g_rowptr[node], eEnd = g_rowptr[node + 1];
    for (; e + 1 < eEnd; e += 2) {
        int s0 = g_col[e], s1 = g_col[e + 1];
        float d0 = g_dinv[s0], d1 = g_dinv[s1];
        float4 x0 = *(const float4*)&x[(size_t)s0 * 128 + lane * 4];
        float4 x1 = *(const float4*)&x[(size_t)s1 * 128 + lane * 4];
        acc.x += x0.x * d0 + x1.x * d1;
        acc.y += x0.y * d0 + x1.y * d1;
        acc.z += x0.z * d0 + x1.z * d1;
        acc.w += x0.w * d0 + x1.w * d1;
    }
    if (e < eEnd) {
        int s0 = g_col[e];
        float d0 = g_dinv[s0];
        float4 x0 = *(const float4*)&x[(size_t)s0 * 128 + lane * 4];
        acc.x += x0.x * d0; acc.y += x0.y * d0;
        acc.z += x0.z * d0; acc.w += x0.w * d0;
    }

    acc.x *= dself; acc.y *= dself; acc.z *= dself; acc.w *= dself;
    uint32_t h01, l01, h23, l23;
    bf16_split2(acc.x, acc.y, h01, l01);
    bf16_split2(acc.z, acc.w, h23, l23);
    size_t o = (size_t)node * 128 + lane * 4;
    *(uint32_t*)&g_a0_hi[o]     = h01;
    *(uint32_t*)&g_a0_hi[o + 2] = h23;
    *(uint32_t*)&g_a0_lo[o]     = l01;
    *(uint32_t*)&g_a0_lo[o + 2] = l23;
}

// ---------------- layer-2 aggregation + fused layer-3 GEMM ----------------
// h2_i = relu(dinv_i*(sum hs2 + self) + b2);  hs3_i = dinv_i * (h2_i @ W3)
__global__ __launch_bounds__(256) void k_agg_out(const float* __restrict__ b2,
                                                 const float* __restrict__ W3) {
    __shared__ float w3s[256];
    if (threadIdx.x < 256) w3s[threadIdx.x] = W3[threadIdx.x];
    __syncthreads();

    int node = (blockIdx.x * blockDim.x + threadIdx.x) >> 5;
    int lane = threadIdx.x & 31;
    if (node >= N_NODES) return;

    float4 acc = *(const float4*)&g_hs2[(size_t)node * 128 + lane * 4];
    int e = g_rowptr[node], eEnd = g_rowptr[node + 1];
    for (; e + 1 < eEnd; e += 2) {
        int s0 = g_col[e], s1 = g_col[e + 1];
        float4 x0 = *(const float4*)&g_hs2[(size_t)s0 * 128 + lane * 4];
        float4 x1 = *(const float4*)&g_hs2[(size_t)s1 * 128 + lane * 4];
        acc.x += x0.x + x1.x;
        acc.y += x0.y + x1.y;
        acc.z += x0.z + x1.z;
        acc.w += x0.w + x1.w;
    }
    if (e < eEnd) {
        int s0 = g_col[e];
        float4 x0 = *(const float4*)&g_hs2[(size_t)s0 * 128 + lane * 4];
        acc.x += x0.x; acc.y += x0.y; acc.z += x0.z; acc.w += x0.w;
    }

    float d = g_dinv[node];
    float4 b = *(const float4*)&b2[lane * 4];
    float o0 = fmaxf(acc.x * d + b.x, 0.f);
    float o1 = fmaxf(acc.y * d + b.y, 0.f);
    float o2 = fmaxf(acc.z * d + b.z, 0.f);
    float o3 = fmaxf(acc.w * d + b.w, 0.f);

    int c = lane * 4;
    float p0 = o0 * w3s[c * 2 + 0] + o1 * w3s[(c + 1) * 2 + 0]
             + o2 * w3s[(c + 2) * 2 + 0] + o3 * w3s[(c + 3) * 2 + 0];
    float p1 = o0 * w3s[c * 2 + 1] + o1 * w3s[(c + 1) * 2 + 1]
             + o2 * w3s[(c + 2) * 2 + 1] + o3 * w3s[(c + 3) * 2 + 1];
    #pragma unroll
    for (int off = 16; off; off >>= 1) {
        p0 += __shfl_down_sync(0xFFFFFFFFu, p0, off);
        p1 += __shfl_down_sync(0xFFFFFFFFu, p1, off);
    }
    if (lane == 0) {
        g_hs3[(size_t)node * 2 + 0] = p0 * d;
        g_hs3[(size_t)node * 2 + 1] = p1 * d;
    }
}

// ---------------- final aggregation + log_softmax (CH=2) ----------------
__global__ __launch_bounds__(256) void k_agg3(const float* __restrict__ b3,
                                              float* __restrict__ out) {
    int i = blockIdx.x * blockDim.x + threadIdx.x;
    if (i >= N_NODES) return;
    float2 acc = *(const float2*)&g_hs3[(size_t)i * 2];
    int e = g_rowptr[i], eE = g_rowptr[i + 1];
    for (; e < eE; e++) {
        int s = g_col[e];
        float2 x = *(const float2*)&g_hs3[(size_t)s * 2];
        acc.x += x.x;
        acc.y += x.y;
    }
    float d = g_dinv[i];
    float v0 = acc.x * d + b3[0];
    float v1 = acc.y * d + b3[1];
    float m = fmaxf(v0, v1);
    float lse = m + logf(expf(v0 - m) + expf(v1 - m));
    out[(size_t)i * 2 + 0] = v0 - lse;
    out[(size_t)i * 2 + 1] = v1 - lse;
}

// ---------------- launch ----------------
extern "C" void kernel_launch(void* const* d_in, const int* in_sizes, int n_in,
                              void* d_out, int out_size) {
    const float* x  = (const float*)d_in[0];
    const float* W1 = (const float*)d_in[1];
    const float* b1 = (const float*)d_in[2];
    const float* W2 = (const float*)d_in[3];
    const float* b2 = (const float*)d_in[4];
    const float* W3 = (const float*)d_in[5];
    const float* b3 = (const float*)d_in[6];
    const int* ei   = (const int*)d_in[7];   // int32 (JAX x64 disabled)
    const int* src  = ei;
    const int* dst  = ei + N_EDGES;
    float* out = (float*)d_out;

    __nv_bfloat16 *a0hi, *a0lo, *h1hi, *h1lo, *wt1hi, *wt1lo, *wt2hi, *wt2lo;
    float* hs2;
    cudaGetSymbolAddress((void**)&a0hi, g_a0_hi);
    cudaGetSymbolAddress((void**)&a0lo, g_a0_lo);
    cudaGetSymbolAddress((void**)&h1hi, g_h1_hi);
    cudaGetSymbolAddress((void**)&h1lo, g_h1_lo);
    cudaGetSymbolAddress((void**)&wt1hi, g_wt1_hi);
    cudaGetSymbolAddress((void**)&wt1lo, g_wt1_lo);
    cudaGetSymbolAddress((void**)&wt2hi, g_wt2_hi);
    cudaGetSymbolAddress((void**)&wt2lo, g_wt2_lo);
    cudaGetSymbolAddress((void**)&hs2, g_hs2);

    const int TB = 256;
    k_split_w<<<256, TB>>>(W1, W2);
    k_zero_counts<<<SCAN_BLKS, TB>>>();
    k_count<<<(N_EDGES + TB - 1) / TB, TB>>>(dst);
    k_scan1<<<SCAN_BLKS, TB>>>();
    k_scan2<<<1, TB>>>();
    k_scan3<<<SCAN_BLKS, TB>>>();
    k_fill<<<(N_EDGES + TB - 1) / TB, TB>>>(src, dst);

    int aggBlocks = (N_NODES * 32 + TB - 1) / TB;

    // ax -> split planes [N,128]
    k_agg0<<<aggBlocks, TB>>>(x);
    // h1 = relu(ax @ W1 + b1) -> split planes [N,256]
    k_gemm<128, 256, 0><<<dim3(N_PAD / 128, 2), TB>>>(a0hi, a0lo, wt1hi, wt1lo, b1,
                                                      h1hi, h1lo, nullptr);
    // hs2 = dinv (.) (h1 @ W2) -> fp32 [N,128]
    k_gemm<256, 128, 1><<<dim3(N_PAD / 128, 1), TB>>>(h1hi, h1lo, wt2hi, wt2lo, nullptr,
                                                      nullptr, nullptr, hs2);
    // h2 = relu(dinv*(agg hs2)+b2); hs3 = dinv*(h2 @ W3)
    k_agg_out<<<aggBlocks, TB>>>(b2, W3);
    // out = log_softmax
    k_agg3<<<SCAN_BLKS, TB>>>(b3, out);
}

// round 8
// speedup vs baseline: 1.9295x; 1.0178x over previous
#include <cuda_runtime.h>
#include <cuda_bf16.h>
#include <math.h>
#include <stdint.h>

#define N_NODES 50000
#define N_EDGES 600000
#define N_PAD   50048   // 391*128
#define IN_CH   128
#define HID1    256
#define HID2    128
#define SCAN_BLKS 196   // ceil(50000/256)

// ---------------- device scratch ----------------
__device__ int   g_counts[N_NODES];
__device__ int   g_rowptr[N_NODES + 1];
__device__ int   g_cursor[N_NODES];
__device__ float g_dinv[N_NODES];
__device__ int   g_col[N_EDGES];
__device__ int   g_bsum[SCAN_BLKS];
__device__ int   g_boff[SCAN_BLKS];

__device__ __align__(16) __nv_bfloat16 g_a0_hi[(size_t)N_PAD * 128];
__device__ __align__(16) __nv_bfloat16 g_a0_lo[(size_t)N_PAD * 128];
__device__ __align__(16) __nv_bfloat16 g_wt1_hi[256 * 128];
__device__ __align__(16) __nv_bfloat16 g_wt1_lo[256 * 128];
__device__ __align__(16) __nv_bfloat16 g_wt2_hi[128 * 256];
__device__ __align__(16) __nv_bfloat16 g_wt2_lo[128 * 256];
__device__ float g_hs2[(size_t)N_NODES * 128];
__device__ float g_hs3[(size_t)N_NODES * 2];

// ---------------- graph construction ----------------
__global__ void k_zero_counts() {
    int i = blockIdx.x * blockDim.x + threadIdx.x;
    if (i < N_NODES) g_counts[i] = 0;
}

__global__ void k_count(const int* __restrict__ dst) {
    int e = blockIdx.x * blockDim.x + threadIdx.x;
    if (e < N_EDGES) atomicAdd(&g_counts[dst[e]], 1);
}

__global__ __launch_bounds__(256) void k_scan1() {
    __shared__ int sh[256];
    int b = blockIdx.x, t = threadIdx.x;
    int i = b * 256 + t;
    int v = (i < N_NODES) ? g_counts[i] : 0;
    sh[t] = v;
    __syncthreads();
    #pragma unroll
    for (int off = 1; off < 256; off <<= 1) {
        int u = (t >= off) ? sh[t - off] : 0;
        __syncthreads();
        sh[t] += u;
        __syncthreads();
    }
    if (i < N_NODES) g_rowptr[i + 1] = sh[t];
    if (t == 255) g_bsum[b] = sh[255];
}

__global__ __launch_bounds__(256) void k_scan2() {
    __shared__ int sh[256];
    int t = threadIdx.x;
    int v = (t < SCAN_BLKS) ? g_bsum[t] : 0;
    sh[t] = v;
    __syncthreads();
    #pragma unroll
    for (int off = 1; off < 256; off <<= 1) {
        int u = (t >= off) ? sh[t - off] : 0;
        __syncthreads();
        sh[t] += u;
        __syncthreads();
    }
    if (t < SCAN_BLKS) g_boff[t] = sh[t] - v;  // exclusive
}

__global__ __launch_bounds__(256) void k_scan3() {
    int b = blockIdx.x, t = threadIdx.x;
    int i = b * 256 + t;
    if (i < N_NODES) {
        int rp1 = g_rowptr[i + 1] + g_boff[b];
        g_rowptr[i + 1] = rp1;
        int c = g_counts[i];
        g_cursor[i] = rp1 - c;
        g_dinv[i] = rsqrtf((float)(c + 1));
    }
    if (i == 0) g_rowptr[0] = 0;
}

__global__ void k_fill(const int* __restrict__ src,
                       const int* __restrict__ dst) {
    int e = blockIdx.x * blockDim.x + threadIdx.x;
    if (e < N_EDGES) {
        int d = dst[e];
        int pos = atomicAdd(&g_cursor[d], 1);
        g_col[pos] = src[e];
    }
}

// ---------------- helpers ----------------
__device__ __forceinline__ void bf16_split2(float a, float b, uint32_t& hi, uint32_t& lo) {
    __nv_bfloat162 h = __floats2bfloat162_rn(a, b);
    hi = *(uint32_t*)&h;
    float ra = a - __bfloat162float(h.x);
    float rb = b - __bfloat162float(h.y);
    __nv_bfloat162 l = __floats2bfloat162_rn(ra, rb);
    lo = *(uint32_t*)&l;
}

__device__ __forceinline__ void mma_bf16(float* c, uint32_t a0, uint32_t a1,
                                         uint32_t a2, uint32_t a3,
                                         uint32_t b0, uint32_t b1) {
    asm volatile(
        "mma.sync.aligned.m16n8k16.row.col.f32.bf16.bf16.f32 "
        "{%0,%1,%2,%3}, {%4,%5,%6,%7}, {%8,%9}, {%0,%1,%2,%3};"
        : "+f"(c[0]), "+f"(c[1]), "+f"(c[2]), "+f"(c[3])
        : "r"(a0), "r"(a1), "r"(a2), "r"(a3), "r"(b0), "r"(b1));
}

__device__ __forceinline__ void cp16(uint32_t saddr, const void* gptr) {
    asm volatile("cp.async.ca.shared.global [%0], [%1], 16;" :: "r"(saddr), "l"(gptr));
}

// ---------------- weight prep: split + transpose W1, W2 into bf16 planes ----------------
__global__ __launch_bounds__(256) void k_split_w(const float* __restrict__ W1,
                                                 const float* __restrict__ W2) {
    int idx = blockIdx.x * blockDim.x + threadIdx.x;
    if (idx < 128 * 256) {
        int k = idx >> 8, m = idx & 255;          // W1[k][m], K=128, M=256
        float v = W1[idx];
        __nv_bfloat16 h = __float2bfloat16_rn(v);
        __nv_bfloat16 l = __float2bfloat16_rn(v - __bfloat162float(h));
        g_wt1_hi[m * 128 + k] = h;
        g_wt1_lo[m * 128 + k] = l;
    } else {
        int j = idx - 128 * 256;
        int k = j >> 7, m = j & 127;              // W2[k][m], K=256, M=128
        float v = W2[j];
        __nv_bfloat16 h = __float2bfloat16_rn(v);
        __nv_bfloat16 l = __float2bfloat16_rn(v - __bfloat162float(h));
        g_wt2_hi[m * 256 + k] = h;
        g_wt2_lo[m * 256 + k] = l;
    }
}

// ---------------- fused GEMM1+GEMM2 (3xBF16 mma.sync, pipelined) ----------------
// Per CTA: 128 rows.
//   phase 1: h1 = relu(ax @ W1 + b1)  [128 x 256] -> split planes in SMEM
//   phase 2: hs2 = dinv * (h1 @ W2)   [128 x 128] -> global fp32
// SMEM (uint32 units):
//   Ah [128*68], Al [128*68]       resident A planes (stride 68: 16B-aligned rows,
//                                  bank pattern gid*4+tig -> conflict-free)
//   H1h [128*132], H1l [128*132]   h1 planes (132 mod 32 = 4 -> conflict-free)
//   STG [2 stages][2 planes][128*12] streamed W tiles (BK=16, 48B rows)
#define AS2 68
#define HS2 132
#define OFF_AL   (128 * AS2)
#define OFF_H1H  (2 * 128 * AS2)
#define OFF_H1L  (OFF_H1H + 128 * HS2)
#define OFF_STG  (OFF_H1L + 128 * HS2)
#define STG_SZ   (2 * 128 * 12)
#define SMEM_U32 (OFF_STG + 2 * STG_SZ)

__global__ __launch_bounds__(256) void k_gemm12(const __nv_bfloat16* __restrict__ a_hi,
                                                const __nv_bfloat16* __restrict__ a_lo,
                                                const __nv_bfloat16* __restrict__ w1h,
                                                const __nv_bfloat16* __restrict__ w1l,
                                                const __nv_bfloat16* __restrict__ w2h,
                                                const __nv_bfloat16* __restrict__ w2l,
                                                const float* __restrict__ b1,
                                                float* __restrict__ hs2) {
    extern __shared__ __align__(16) uint32_t sm[];

    const int tid  = threadIdx.x;
    const int lane = tid & 31;
    const int warp = tid >> 5;
    const int gid  = lane >> 2;
    const int tig  = lane & 3;
    const int warpM = warp & 3;
    const int warpN = warp >> 2;
    const int rowBase = blockIdx.x * 128;

    const uint32_t sb = (uint32_t)__cvta_generic_to_shared(sm);

    // resident A planes: 128 rows x 128 bf16 x 2 planes = 4096 16B-chunks
    for (int u = tid; u < 4096; u += 256) {
        int p = u >> 11;
        int v = u & 2047;
        int r = v >> 4, ch = v & 15;
        const __nv_bfloat16* g = (p ? a_lo : a_hi) + (size_t)(rowBase + r) * 128 + ch * 8;
        uint32_t d = sb + (uint32_t)(((p ? OFF_AL : 0) + r * AS2 + ch * 4) << 2);
        cp16(d, g);
    }

    // stream one 128x16 hi/lo W tile pair into stage s
    auto loadB = [&](int s, const __nv_bfloat16* bh, const __nv_bfloat16* bl,
                     int mBase, int Kb, int kBase) {
        int r = tid >> 1, ch = tid & 1;
        size_t go = (size_t)(mBase + r) * Kb + kBase + ch * 8;
        uint32_t d = sb + (uint32_t)((OFF_STG + s * STG_SZ + r * 12 + ch * 4) << 2);
        cp16(d, bh + go);
        cp16(d + (uint32_t)((128 * 12) << 2), bl + go);
    };

    float acc[2][8][4];

    // =================== phase 1: two column blocks of h1 ===================
    #pragma unroll 1
    for (int cb = 0; cb < 2; cb++) {
        #pragma unroll
        for (int mt = 0; mt < 2; mt++)
            #pragma unroll
            for (int nt = 0; nt < 8; nt++)
                #pragma unroll
                for (int j = 0; j < 4; j++) acc[mt][nt][j] = 0.f;

        loadB(0, w1h, w1l, cb * 128, 128, 0);
        asm volatile("cp.async.commit_group;");

        #pragma unroll 1
        for (int i = 0; i < 8; i++) {
            if (i < 7) {
                loadB((i + 1) & 1, w1h, w1l, cb * 128, 128, (i + 1) * 16);
                asm volatile("cp.async.commit_group;");
                asm volatile("cp.async.wait_group 1;");
            } else {
                asm volatile("cp.async.wait_group 0;");
            }
            __syncthreads();

            const uint32_t* Bh = &sm[OFF_STG + (i & 1) * STG_SZ];
            const uint32_t* Bl = Bh + 128 * 12;
            const int ks = i * 8;

            uint32_t ahi[2][4], alo[2][4];
            #pragma unroll
            for (int mt = 0; mt < 2; mt++) {
                int r0 = warpM * 32 + mt * 16 + gid;
                ahi[mt][0] = sm[r0 * AS2 + ks + tig];
                ahi[mt][1] = sm[(r0 + 8) * AS2 + ks + tig];
                ahi[mt][2] = sm[r0 * AS2 + ks + tig + 4];
                ahi[mt][3] = sm[(r0 + 8) * AS2 + ks + tig + 4];
                alo[mt][0] = sm[OFF_AL + r0 * AS2 + ks + tig];
                alo[mt][1] = sm[OFF_AL + (r0 + 8) * AS2 + ks + tig];
                alo[mt][2] = sm[OFF_AL + r0 * AS2 + ks + tig + 4];
                alo[mt][3] = sm[OFF_AL + (r0 + 8) * AS2 + ks + tig + 4];
            }
            #pragma unroll
            for (int nt = 0; nt < 8; nt++) {
                int c0 = warpN * 64 + nt * 8 + gid;
                uint32_t bh0 = Bh[c0 * 12 + tig], bh1 = Bh[c0 * 12 + tig + 4];
                uint32_t bl0 = Bl[c0 * 12 + tig], bl1 = Bl[c0 * 12 + tig + 4];
                #pragma unroll
                for (int mt = 0; mt < 2; mt++) {
                    mma_bf16(acc[mt][nt], ahi[mt][0], ahi[mt][1], ahi[mt][2], ahi[mt][3], bh0, bh1);
                    mma_bf16(acc[mt][nt], ahi[mt][0], ahi[mt][1], ahi[mt][2], ahi[mt][3], bl0, bl1);
                    mma_bf16(acc[mt][nt], alo[mt][0], alo[mt][1], alo[mt][2], alo[mt][3], bh0, bh1);
                }
            }
            __syncthreads();
        }

        // epilogue: relu + bias, split into H1 planes
        #pragma unroll
        for (int mt = 0; mt < 2; mt++) {
            int rl = warpM * 32 + mt * 16 + gid;
            #pragma unroll
            for (int nt = 0; nt < 8; nt++) {
                int col = cb * 128 + warpN * 64 + nt * 8 + 2 * tig;
                int cidx = col >> 1;
                float bb0 = b1[col], bb1 = b1[col + 1];
                float* c = acc[mt][nt];
                uint32_t h, l;
                float v0 = fmaxf(c[0] + bb0, 0.f), v1 = fmaxf(c[1] + bb1, 0.f);
                bf16_split2(v0, v1, h, l);
                sm[OFF_H1H + rl * HS2 + cidx] = h;
                sm[OFF_H1L + rl * HS2 + cidx] = l;
                v0 = fmaxf(c[2] + bb0, 0.f); v1 = fmaxf(c[3] + bb1, 0.f);
                bf16_split2(v0, v1, h, l);
                sm[OFF_H1H + (rl + 8) * HS2 + cidx] = h;
                sm[OFF_H1L + (rl + 8) * HS2 + cidx] = l;
            }
        }
    }

    // =================== phase 2: hs2 = dinv * (h1 @ W2) ===================
    #pragma unroll
    for (int mt = 0; mt < 2; mt++)
        #pragma unroll
        for (int nt = 0; nt < 8; nt++)
            #pragma unroll
            for (int j = 0; j < 4; j++) acc[mt][nt][j] = 0.f;

    loadB(0, w2h, w2l, 0, 256, 0);
    asm volatile("cp.async.commit_group;");

    #pragma unroll 1
    for (int i = 0; i < 16; i++) {
        if (i < 15) {
            loadB((i + 1) & 1, w2h, w2l, 0, 256, (i + 1) * 16);
            asm volatile("cp.async.commit_group;");
            asm volatile("cp.async.wait_group 1;");
        } else {
            asm volatile("cp.async.wait_group 0;");
        }
        __syncthreads();   // also orders H1 writes before first reads

        const uint32_t* Bh = &sm[OFF_STG + (i & 1) * STG_SZ];
        const uint32_t* Bl = Bh + 128 * 12;
        const int ks = i * 8;

        uint32_t ahi[2][4], alo[2][4];
        #pragma unroll
        for (int mt = 0; mt < 2; mt++) {
            int r0 = warpM * 32 + mt * 16 + gid;
            ahi[mt][0] = sm[OFF_H1H + r0 * HS2 + ks + tig];
            ahi[mt][1] = sm[OFF_H1H + (r0 + 8) * HS2 + ks + tig];
            ahi[mt][2] = sm[OFF_H1H + r0 * HS2 + ks + tig + 4];
            ahi[mt][3] = sm[OFF_H1H + (r0 + 8) * HS2 + ks + tig + 4];
            alo[mt][0] = sm[OFF_H1L + r0 * HS2 + ks + tig];
            alo[mt][1] = sm[OFF_H1L + (r0 + 8) * HS2 + ks + tig];
            alo[mt][2] = sm[OFF_H1L + r0 * HS2 + ks + tig + 4];
            alo[mt][3] = sm[OFF_H1L + (r0 + 8) * HS2 + ks + tig + 4];
        }
        #pragma unroll
        for (int nt = 0; nt < 8; nt++) {
            int c0 = warpN * 64 + nt * 8 + gid;
            uint32_t bh0 = Bh[c0 * 12 + tig], bh1 = Bh[c0 * 12 + tig + 4];
            uint32_t bl0 = Bl[c0 * 12 + tig], bl1 = Bl[c0 * 12 + tig + 4];
            #pragma unroll
            for (int mt = 0; mt < 2; mt++) {
                mma_bf16(acc[mt][nt], ahi[mt][0], ahi[mt][1], ahi[mt][2], ahi[mt][3], bh0, bh1);
                mma_bf16(acc[mt][nt], ahi[mt][0], ahi[mt][1], ahi[mt][2], ahi[mt][3], bl0, bl1);
                mma_bf16(acc[mt][nt], alo[mt][0], alo[mt][1], alo[mt][2], alo[mt][3], bh0, bh1);
            }
        }
        __syncthreads();
    }

    // epilogue: dinv scale -> global
    #pragma unroll
    for (int mt = 0; mt < 2; mt++) {
        int r0 = rowBase + warpM * 32 + mt * 16 + gid;
        #pragma unroll
        for (int nt = 0; nt < 8; nt++) {
            int col = warpN * 64 + nt * 8 + 2 * tig;
            float* c = acc[mt][nt];
            if (r0 < N_NODES) {
                float d = g_dinv[r0];
                *(float2*)&hs2[(size_t)r0 * 128 + col] = make_float2(c[0] * d, c[1] * d);
            }
            if (r0 + 8 < N_NODES) {
                float d = g_dinv[r0 + 8];
                *(float2*)&hs2[(size_t)(r0 + 8) * 128 + col] = make_float2(c[2] * d, c[3] * d);
            }
        }
    }
}

// ---------------- layer-0 aggregation -> split bf16 planes ----------------
__global__ __launch_bounds__(256) void k_agg0(const float* __restrict__ x) {
    int node = (blockIdx.x * blockDim.x + threadIdx.x) >> 5;
    int lane = threadIdx.x & 31;
    if (node >= N_NODES) return;

    float dself = g_dinv[node];
    float4 acc = *(const float4*)&x[(size_t)node * 128 + lane * 4];
    acc.x *= dself; acc.y *= dself; acc.z *= dself; acc.w *= dself;

    int e = g_rowptr[node], eEnd = g_rowptr[node + 1];
    for (; e + 1 < eEnd; e += 2) {
        int s0 = g_col[e], s1 = g_col[e + 1];
        float d0 = g_dinv[s0], d1 = g_dinv[s1];
        float4 x0 = *(const float4*)&x[(size_t)s0 * 128 + lane * 4];
        float4 x1 = *(const float4*)&x[(size_t)s1 * 128 + lane * 4];
        acc.x += x0.x * d0 + x1.x * d1;
        acc.y += x0.y * d0 + x1.y * d1;
        acc.z += x0.z * d0 + x1.z * d1;
        acc.w += x0.w * d0 + x1.w * d1;
    }
    if (e < eEnd) {
        int s0 = g_col[e];
        float d0 = g_dinv[s0];
        float4 x0 = *(const float4*)&x[(size_t)s0 * 128 + lane * 4];
        acc.x += x0.x * d0; acc.y += x0.y * d0;
        acc.z += x0.z * d0; acc.w += x0.w * d0;
    }

    acc.x *= dself; acc.y *= dself; acc.z *= dself; acc.w *= dself;
    uint32_t h01, l01, h23, l23;
    bf16_split2(acc.x, acc.y, h01, l01);
    bf16_split2(acc.z, acc.w, h23, l23);
    size_t o = (size_t)node * 128 + lane * 4;
    *(uint32_t*)&g_a0_hi[o]     = h01;
    *(uint32_t*)&g_a0_hi[o + 2] = h23;
    *(uint32_t*)&g_a0_lo[o]     = l01;
    *(uint32_t*)&g_a0_lo[o + 2] = l23;
}

// ---------------- layer-2 aggregation + fused layer-3 GEMM ----------------
__global__ __launch_bounds__(256) void k_agg_out(const float* __restrict__ b2,
                                                 const float* __restrict__ W3) {
    __shared__ float w3s[256];
    if (threadIdx.x < 256) w3s[threadIdx.x] = W3[threadIdx.x];
    __syncthreads();

    int node = (blockIdx.x * blockDim.x + threadIdx.x) >> 5;
    int lane = threadIdx.x & 31;
    if (node >= N_NODES) return;

    float4 acc = *(const float4*)&g_hs2[(size_t)node * 128 + lane * 4];
    int e = g_rowptr[node], eEnd = g_rowptr[node + 1];
    for (; e + 1 < eEnd; e += 2) {
        int s0 = g_col[e], s1 = g_col[e + 1];
        float4 x0 = *(const float4*)&g_hs2[(size_t)s0 * 128 + lane * 4];
        float4 x1 = *(const float4*)&g_hs2[(size_t)s1 * 128 + lane * 4];
        acc.x += x0.x + x1.x;
        acc.y += x0.y + x1.y;
        acc.z += x0.z + x1.z;
        acc.w += x0.w + x1.w;
    }
    if (e < eEnd) {
        int s0 = g_col[e];
        float4 x0 = *(const float4*)&g_hs2[(size_t)s0 * 128 + lane * 4];
        acc.x += x0.x; acc.y += x0.y; acc.z += x0.z; acc.w += x0.w;
    }

    float d = g_dinv[node];
    float4 b = *(const float4*)&b2[lane * 4];
    float o0 = fmaxf(acc.x * d + b.x, 0.f);
    float o1 = fmaxf(acc.y * d + b.y, 0.f);
    float o2 = fmaxf(acc.z * d + b.z, 0.f);
    float o3 = fmaxf(acc.w * d + b.w, 0.f);

    int c = lane * 4;
    float p0 = o0 * w3s[c * 2 + 0] + o1 * w3s[(c + 1) * 2 + 0]
             + o2 * w3s[(c + 2) * 2 + 0] + o3 * w3s[(c + 3) * 2 + 0];
    float p1 = o0 * w3s[c * 2 + 1] + o1 * w3s[(c + 1) * 2 + 1]
             + o2 * w3s[(c + 2) * 2 + 1] + o3 * w3s[(c + 3) * 2 + 1];
    #pragma unroll
    for (int off = 16; off; off >>= 1) {
        p0 += __shfl_down_sync(0xFFFFFFFFu, p0, off);
        p1 += __shfl_down_sync(0xFFFFFFFFu, p1, off);
    }
    if (lane == 0) {
        g_hs3[(size_t)node * 2 + 0] = p0 * d;
        g_hs3[(size_t)node * 2 + 1] = p1 * d;
    }
}

// ---------------- final aggregation + log_softmax (CH=2) ----------------
__global__ __launch_bounds__(256) void k_agg3(const float* __restrict__ b3,
                                              float* __restrict__ out) {
    int i = blockIdx.x * blockDim.x + threadIdx.x;
    if (i >= N_NODES) return;
    float2 acc = *(const float2*)&g_hs3[(size_t)i * 2];
    int e = g_rowptr[i], eE = g_rowptr[i + 1];
    for (; e < eE; e++) {
        int s = g_col[e];
        float2 x = *(const float2*)&g_hs3[(size_t)s * 2];
        acc.x += x.x;
        acc.y += x.y;
    }
    float d = g_dinv[i];
    float v0 = acc.x * d + b3[0];
    float v1 = acc.y * d + b3[1];
    float m = fmaxf(v0, v1);
    float lse = m + logf(expf(v0 - m) + expf(v1 - m));
    out[(size_t)i * 2 + 0] = v0 - lse;
    out[(size_t)i * 2 + 1] = v1 - lse;
}

// ---------------- launch ----------------
extern "C" void kernel_launch(void* const* d_in, const int* in_sizes, int n_in,
                              void* d_out, int out_size) {
    const float* x  = (const float*)d_in[0];
    const float* W1 = (const float*)d_in[1];
    const float* b1 = (const float*)d_in[2];
    const float* W2 = (const float*)d_in[3];
    const float* b2 = (const float*)d_in[4];
    const float* W3 = (const float*)d_in[5];
    const float* b3 = (const float*)d_in[6];
    const int* ei   = (const int*)d_in[7];   // int32 (JAX x64 disabled)
    const int* src  = ei;
    const int* dst  = ei + N_EDGES;
    float* out = (float*)d_out;

    __nv_bfloat16 *a0hi, *a0lo, *wt1hi, *wt1lo, *wt2hi, *wt2lo;
    float* hs2;
    cudaGetSymbolAddress((void**)&a0hi, g_a0_hi);
    cudaGetSymbolAddress((void**)&a0lo, g_a0_lo);
    cudaGetSymbolAddress((void**)&wt1hi, g_wt1_hi);
    cudaGetSymbolAddress((void**)&wt1lo, g_wt1_lo);
    cudaGetSymbolAddress((void**)&wt2hi, g_wt2_hi);
    cudaGetSymbolAddress((void**)&wt2lo, g_wt2_lo);
    cudaGetSymbolAddress((void**)&hs2, g_hs2);

    const int smemBytes = SMEM_U32 * 4;   // 229376 B (< 232448 opt-in cap)
    cudaFuncSetAttribute(k_gemm12, cudaFuncAttributeMaxDynamicSharedMemorySize, smemBytes);

    const int TB = 256;
    k_split_w<<<256, TB>>>(W1, W2);
    k_zero_counts<<<SCAN_BLKS, TB>>>();
    k_count<<<(N_EDGES + TB - 1) / TB, TB>>>(dst);
    k_scan1<<<SCAN_BLKS, TB>>>();
    k_scan2<<<1, TB>>>();
    k_scan3<<<SCAN_BLKS, TB>>>();
    k_fill<<<(N_EDGES + TB - 1) / TB, TB>>>(src, dst);

    int aggBlocks = (N_NODES * 32 + TB - 1) / TB;

    // ax -> split planes [N,128]
    k_agg0<<<aggBlocks, TB>>>(x);
    // h1 = relu(ax@W1+b1); hs2 = dinv*(h1@W2)  (fused, h1 stays in SMEM)
    k_gemm12<<<N_PAD / 128, TB, smemBytes>>>(a0hi, a0lo, wt1hi, wt1lo, wt2hi, wt2lo, b1, hs2);
    // h2 = relu(dinv*(agg hs2)+b2); hs3 = dinv*(h2 @ W3)
    k_agg_out<<<aggBlocks, TB>>>(b2, W3);
    // out = log_softmax
    k_agg3<<<SCAN_BLKS, TB>>>(b3, out);
}